// round 17
// baseline (speedup 1.0000x reference)
#include <cuda_runtime.h>
#include <cuda_bf16.h>
#include <math.h>
#include <stdint.h>

#define NB 4
#define BATCH 2
#define HW 4096
#define F 64
#define LOG2E 1.4426950408889634f

// ---------------- scratch (device globals; no allocation allowed) ----------
__device__ float    g_fused[BATCH * HW * 256];
__device__ uint32_t g_q[BATCH * NB * HW * 4];       // f16x2 pairs [pos][4]
__device__ uint32_t g_k[BATCH * NB * HW * 4];       // f16x2 pairs
__device__ uint32_t g_vp[BATCH * NB * 32 * 4096];   // f16x2 pairs, ldmatrix order
__device__ float    g_pool[NB * BATCH * HW * 16];

// ---------------- helpers ---------------------------------------------------
__device__ __forceinline__ uint32_t f2tf32(float f) {
    uint32_t r; asm("cvt.rna.tf32.f32 %0, %1;" : "=r"(r) : "f"(f)); return r;
}
__device__ __forceinline__ uint32_t packh(float hi, float lo) {
    uint32_t r; asm("cvt.rn.f16x2.f32 %0, %1, %2;" : "=r"(r) : "f"(hi), "f"(lo)); return r;
}
__device__ __forceinline__ uint32_t ex2h2(uint32_t x) {
    uint32_t y; asm("ex2.approx.f16x2 %0, %1;" : "=r"(y) : "r"(x)); return y;
}
__device__ __forceinline__ void mma_tf32(float c[4], uint32_t a0, uint32_t a1,
                                         uint32_t a2, uint32_t a3,
                                         uint32_t b0, uint32_t b1) {
    asm volatile(
        "mma.sync.aligned.m16n8k8.row.col.f32.tf32.tf32.f32 "
        "{%0,%1,%2,%3},{%4,%5,%6,%7},{%8,%9},{%0,%1,%2,%3};"
        : "+f"(c[0]), "+f"(c[1]), "+f"(c[2]), "+f"(c[3])
        : "r"(a0), "r"(a1), "r"(a2), "r"(a3), "r"(b0), "r"(b1));
}
__device__ __forceinline__ void mma_f16(float c[4], uint32_t a0, uint32_t a1,
                                        uint32_t a2, uint32_t a3,
                                        uint32_t b0, uint32_t b1) {
    asm volatile(
        "mma.sync.aligned.m16n8k16.row.col.f32.f16.f16.f32 "
        "{%0,%1,%2,%3},{%4,%5,%6,%7},{%8,%9},{%0,%1,%2,%3};"
        : "+f"(c[0]), "+f"(c[1]), "+f"(c[2]), "+f"(c[3])
        : "r"(a0), "r"(a1), "r"(a2), "r"(a3), "r"(b0), "r"(b1));
}
// QK: f16 accumulator -> scores arrive pre-packed as f16x2
__device__ __forceinline__ void mma_f16k8h(uint32_t& d0, uint32_t& d1,
                                           uint32_t a0, uint32_t a1, uint32_t b0) {
    asm volatile(
        "mma.sync.aligned.m16n8k8.row.col.f16.f16.f16.f16 "
        "{%0,%1},{%2,%3},{%4},{%5,%6};"
        : "=r"(d0), "=r"(d1)
        : "r"(a0), "r"(a1), "r"(b0), "r"(0u), "r"(0u));
}
__device__ __forceinline__ void ldsm_x4(uint32_t& r0, uint32_t& r1,
                                        uint32_t& r2, uint32_t& r3, uint32_t addr) {
    asm volatile("ldmatrix.sync.aligned.m8n8.x4.shared.b16 {%0,%1,%2,%3}, [%4];"
        : "=r"(r0), "=r"(r1), "=r"(r2), "=r"(r3) : "r"(addr));
}
__device__ __forceinline__ void cpa16(uint32_t s, const void* g) {
    asm volatile("cp.async.cg.shared.global [%0], [%1], 16;" :: "r"(s), "l"(g));
}
__device__ __forceinline__ void cpa16z(uint32_t s, const void* g, int sz) {
    asm volatile("cp.async.cg.shared.global [%0], [%1], 16, %2;" :: "r"(s), "l"(g), "r"(sz));
}

// ---------------- K1: dilated conv + fused QKV (unchanged) -----------------
__global__ void __launch_bounds__(256, 2) k_conv(
        const float* __restrict__ x, const float* __restrict__ wg,
        const float* __restrict__ cb, const float* __restrict__ bg,
        const float* __restrict__ bbe, const float* __restrict__ bm,
        const float* __restrict__ bv,
        const float* __restrict__ qw, const float* __restrict__ qb,
        const float* __restrict__ kw, const float* __restrict__ kb_,
        const float* __restrict__ vw, const float* __restrict__ vb) {
    extern __shared__ uint32_t dyn[];
    uint32_t* Vt = dyn + 8704;
    uint32_t* QW = dyn + 12928;
    uint32_t* KW = dyn + 13472;
    float* vbs = (float*)(dyn + 14016);
    float* qkb = (float*)(dyn + 14080);
    float* scs = (float*)(dyn + 26112);
    float* shs = (float*)(dyn + 26176);

    int tid = threadIdx.x;
    int bb = blockIdx.y, b = bb >> 2, br = bb & 3;
    int d = 1 << br;
    int pix0 = blockIdx.x * 128;
    int y0 = blockIdx.x * 2;

    if (tid < 64) {
        int idx = br * 64 + tid;
        float sc = bg[idx] * rsqrtf(bv[idx] + 1e-3f);
        scs[tid] = sc;
        shs[tid] = bbe[idx] - bm[idx] * sc + cb[idx] * sc;
    }

    int w = tid >> 5, lane = tid & 31;
    int g = lane >> 2, t = lane & 3;
    int m0 = w * 16;

    float c[8][4];
#pragma unroll
    for (int nb = 0; nb < 8; ++nb) c[nb][0] = c[nb][1] = c[nb][2] = c[nb][3] = 0.f;

    int p = tid >> 1, ch = (tid & 1) * 32;
    int prow = p >> 6, pcol = p & 63;
    int wci0 = tid >> 4, wco4 = (tid & 15) * 4;

    uint32_t sh0 = (uint32_t)__cvta_generic_to_shared(dyn);
    uint32_t a_dst0 = sh0 + (uint32_t)((p * 68 + ch) * 4);
    const float* xb = x + (size_t)b * 64 * 64 * 64;
    const float* wbase = wg + (size_t)br * 9 * 4096;

#define PREFETCH_A(tap, bi) do {                                             \
        int ky_ = (tap) / 3, kx_ = (tap) - ky_ * 3;                          \
        int iy_ = y0 + prow + d * (ky_ - 1);                                 \
        int ix_ = pcol + d * (kx_ - 1);                                      \
        int val_ = (((unsigned)iy_ < 64u) & ((unsigned)ix_ < 64u)) ? 16 : 0; \
        int iyc_ = min(max(iy_, 0), 63), ixc_ = min(max(ix_, 0), 63);        \
        const float* asrc_ = xb + (((size_t)iyc_ * 64 + ixc_) * 64 + ch);    \
        uint32_t ad_ = a_dst0 + (uint32_t)(bi) * 34816u;                     \
        _Pragma("unroll")                                                    \
        for (int i_ = 0; i_ < 8; ++i_) cpa16z(ad_ + i_ * 16, asrc_ + i_ * 4, val_); \
        asm volatile("cp.async.commit_group;");                              \
    } while (0)

    PREFETCH_A(0, 0);
    PREFETCH_A(1, 1);
    {
        uint32_t* W0 = dyn + 17408;
#pragma unroll
        for (int i = 0; i < 4; ++i) {
            int ci = wci0 + i * 16;
            float4 v = *(const float4*)(wbase + ci * 64 + wco4);
            W0[(wco4 + 0) * 68 + ci] = f2tf32(v.x);
            W0[(wco4 + 1) * 68 + ci] = f2tf32(v.y);
            W0[(wco4 + 2) * 68 + ci] = f2tf32(v.z);
            W0[(wco4 + 3) * 68 + ci] = f2tf32(v.w);
        }
    }
    asm volatile("cp.async.wait_group 1;");
    __syncthreads();

#pragma unroll 1
    for (int tap = 0; tap < 9; ++tap) {
        float4 wr[4];
        if (tap + 1 < 9) {
            const float* wt1 = wbase + (size_t)(tap + 1) * 4096;
#pragma unroll
            for (int i = 0; i < 4; ++i)
                wr[i] = *(const float4*)(wt1 + (wci0 + i * 16) * 64 + wco4);
        }
        const uint32_t* Ab = dyn + (tap & 1) * 8704;
        const uint32_t* Wb = dyn + 17408 + (tap & 1) * 4352;
        const uint32_t* Ar0 = Ab + (m0 + g) * 68 + t;
        const uint32_t* Ar1 = Ab + (m0 + g + 8) * 68 + t;
        const uint32_t* Wg_ = Wb + g * 68 + t;
#pragma unroll
        for (int k0 = 0; k0 < 64; k0 += 8) {
            uint32_t a0 = Ar0[k0], a1 = Ar1[k0];
            uint32_t a2 = Ar0[k0 + 4], a3 = Ar1[k0 + 4];
#pragma unroll
            for (int nb = 0; nb < 8; ++nb)
                mma_tf32(c[nb], a0, a1, a2, a3,
                         Wg_[nb * 8 * 68 + k0], Wg_[nb * 8 * 68 + k0 + 4]);
        }
        if (tap + 1 < 9) {
            uint32_t* Wn = dyn + 17408 + ((tap + 1) & 1) * 4352;
#pragma unroll
            for (int i = 0; i < 4; ++i) {
                int ci = wci0 + i * 16;
                Wn[(wco4 + 0) * 68 + ci] = f2tf32(wr[i].x);
                Wn[(wco4 + 1) * 68 + ci] = f2tf32(wr[i].y);
                Wn[(wco4 + 2) * 68 + ci] = f2tf32(wr[i].z);
                Wn[(wco4 + 3) * 68 + ci] = f2tf32(wr[i].w);
            }
        }
        __syncthreads();
        if (tap + 2 < 9) {
            PREFETCH_A(tap + 2, (tap & 1));
            asm volatile("cp.async.wait_group 1;");
            __syncthreads();
        } else if (tap + 1 < 9) {
            asm volatile("cp.async.wait_group 0;");
            __syncthreads();
        }
    }
#undef PREFETCH_A

    float rv[8][4];
    float* f0 = g_fused + ((size_t)b * HW + pix0 + m0 + g) * 256 + br * 64;
    float* f1 = f0 + 8 * 256;
#pragma unroll
    for (int nb = 0; nb < 8; ++nb) {
        int col = nb * 8 + 2 * t;
        rv[nb][0] = fmaxf(c[nb][0] * scs[col] + shs[col], 0.f);
        rv[nb][1] = fmaxf(c[nb][1] * scs[col + 1] + shs[col + 1], 0.f);
        rv[nb][2] = fmaxf(c[nb][2] * scs[col] + shs[col], 0.f);
        rv[nb][3] = fmaxf(c[nb][3] * scs[col + 1] + shs[col + 1], 0.f);
        *(float2*)(f0 + col) = make_float2(rv[nb][0], rv[nb][1]);
        *(float2*)(f1 + col) = make_float2(rv[nb][2], rv[nb][3]);
    }
    __syncthreads();
    uint32_t* As = dyn;
#pragma unroll
    for (int nb = 0; nb < 8; ++nb) {
        int col = nb * 8 + 2 * t;
        *(uint2*)&As[(m0 + g) * 68 + col] =
            make_uint2(f2tf32(rv[nb][0]), f2tf32(rv[nb][1]));
        *(uint2*)&As[(m0 + g + 8) * 68 + col] =
            make_uint2(f2tf32(rv[nb][2]), f2tf32(rv[nb][3]));
    }
    uint32_t* Wv = dyn + 17408;
#pragma unroll
    for (int i = 0; i < 4; ++i) {
        int ci = wci0 + i * 16;
        float4 v = *(const float4*)(vw + br * 4096 + ci * 64 + wco4);
        Wv[(wco4 + 0) * 68 + ci] = f2tf32(v.x);
        Wv[(wco4 + 1) * 68 + ci] = f2tf32(v.y);
        Wv[(wco4 + 2) * 68 + ci] = f2tf32(v.z);
        Wv[(wco4 + 3) * 68 + ci] = f2tf32(v.w);
    }
    if (tid < 128) {
        int ci = tid >> 1, d4 = (tid & 1) * 4;
        float4 v = *(const float4*)(qw + br * 512 + ci * 8 + d4);
        QW[(d4 + 0) * 68 + ci] = f2tf32(v.x * LOG2E);
        QW[(d4 + 1) * 68 + ci] = f2tf32(v.y * LOG2E);
        QW[(d4 + 2) * 68 + ci] = f2tf32(v.z * LOG2E);
        QW[(d4 + 3) * 68 + ci] = f2tf32(v.w * LOG2E);
    } else {
        int id = tid - 128;
        int ci = id >> 1, d4 = (id & 1) * 4;
        float4 v = *(const float4*)(kw + br * 512 + ci * 8 + d4);
        KW[(d4 + 0) * 68 + ci] = f2tf32(v.x);
        KW[(d4 + 1) * 68 + ci] = f2tf32(v.y);
        KW[(d4 + 2) * 68 + ci] = f2tf32(v.z);
        KW[(d4 + 3) * 68 + ci] = f2tf32(v.w);
    }
    if (tid < 64) vbs[tid] = vb[br * 64 + tid];
    if (tid >= 64 && tid < 72) qkb[tid - 64] = qb[br * 8 + tid - 64] * LOG2E;
    if (tid >= 72 && tid < 80) qkb[8 + tid - 72] = kb_[br * 8 + tid - 72];
    __syncthreads();
    const uint32_t* Ar0 = As + (m0 + g) * 68 + t;
    const uint32_t* Ar1 = As + (m0 + g + 8) * 68 + t;
    const uint32_t* Wg_ = Wv + g * 68 + t;
    float vac[8][4];
#pragma unroll
    for (int nb = 0; nb < 8; ++nb) vac[nb][0] = vac[nb][1] = vac[nb][2] = vac[nb][3] = 0.f;
#pragma unroll
    for (int k0 = 0; k0 < 64; k0 += 8) {
        uint32_t a0 = Ar0[k0], a1 = Ar1[k0];
        uint32_t a2 = Ar0[k0 + 4], a3 = Ar1[k0 + 4];
#pragma unroll
        for (int nb = 0; nb < 8; ++nb)
            mma_tf32(vac[nb], a0, a1, a2, a3, Wg_[nb * 8 * 68 + k0], Wg_[nb * 8 * 68 + k0 + 4]);
    }
    float qa_[4] = {0.f, 0.f, 0.f, 0.f}, ka_[4] = {0.f, 0.f, 0.f, 0.f};
    const uint32_t* Qg_ = QW + g * 68 + t;
    const uint32_t* Kg_ = KW + g * 68 + t;
#pragma unroll
    for (int k0 = 0; k0 < 64; k0 += 8) {
        uint32_t a0 = Ar0[k0], a1 = Ar1[k0];
        uint32_t a2 = Ar0[k0 + 4], a3 = Ar1[k0 + 4];
        mma_tf32(qa_, a0, a1, a2, a3, Qg_[k0], Qg_[k0 + 4]);
        mma_tf32(ka_, a0, a1, a2, a3, Kg_[k0], Kg_[k0 + 4]);
    }
    {
        float b0f = qkb[2 * t], b1f = qkb[2 * t + 1];
        uint32_t* qd = g_q + ((size_t)bb * HW + pix0 + m0 + g) * 4 + t;
        qd[0]  = packh(qa_[1] + b1f, qa_[0] + b0f);
        qd[32] = packh(qa_[3] + b1f, qa_[2] + b0f);
        float c0f = qkb[8 + 2 * t], c1f = qkb[8 + 2 * t + 1];
        uint32_t* kd = g_k + ((size_t)bb * HW + pix0 + m0 + g) * 4 + t;
        kd[0]  = packh(ka_[1] + c1f, ka_[0] + c0f);
        kd[32] = packh(ka_[3] + c1f, ka_[2] + c0f);
    }
#pragma unroll
    for (int nb = 0; nb < 8; ++nb) {
        int col = nb * 8 + 2 * t;
        Vt[(m0 + g) * 33 + nb * 4 + t] =
            packh(vac[nb][1] + vbs[col + 1], vac[nb][0] + vbs[col]);
        Vt[(m0 + g + 8) * 33 + nb * 4 + t] =
            packh(vac[nb][3] + vbs[col + 1], vac[nb][2] + vbs[col]);
    }
    __syncthreads();
    uint32_t* vout = g_vp + ((size_t)bb * 32 + blockIdx.x) * 4096;
#pragma unroll
    for (int i = 0; i < 16; ++i) {
        int o = tid + i * 256;
        int col = o & 3, row = (o >> 2) & 7, mat = o >> 5;
        int kpt = ((mat >> 3) << 2) | col;
        int cch = ((mat & 7) << 3) | row;
        uint32_t lo = Vt[(2 * kpt) * 33 + (cch >> 1)];
        uint32_t hi = Vt[(2 * kpt + 1) * 33 + (cch >> 1)];
        vout[o] = (cch & 1) ? ((lo >> 16) | (hi & 0xFFFF0000u))
                            : ((lo & 0xFFFFu) | (hi << 16));
    }
}

// ---------------- K3: flash attention, BM=256 (2 query blocks/CTA) ---------
// dyn smem (words): Qs @0 (1024), Ks @1024 (3x512), Vs @2560 (3x4096) = 14848
__global__ void __launch_bounds__(256) k_attn(const float* __restrict__ gamma) {
    extern __shared__ uint32_t dsh[];
    uint32_t* Qs = dsh;
    int tid = threadIdx.x;
    int br = blockIdx.y, b = blockIdx.z;
    int bb = b * NB + br;
    int n0 = blockIdx.x * 256;
    int w = tid >> 5, lane = tid & 31;
    int g = lane >> 2, t = lane & 3;

    const uint32_t* kgm = g_k + (size_t)bb * HW * 4;
    const uint32_t* vgm = g_vp + (size_t)bb * 32 * 4096;

    uint32_t shb = (uint32_t)__cvta_generic_to_shared(dsh);
    uint32_t ksa[3], vsa[3];
#pragma unroll
    for (int i = 0; i < 3; ++i) {
        ksa[i] = shb + (1024u + i * 512u) * 4u;
        vsa[i] = shb + (2560u + i * 4096u) * 4u;
    }

    if (tid < 128) cpa16(ksa[0] + tid * 16, kgm + tid * 4);
#pragma unroll
    for (int j = 0; j < 4; ++j)
        cpa16(vsa[0] + (tid + j * 256) * 16, vgm + (tid + j * 256) * 4);
    asm volatile("cp.async.commit_group;");
    ((uint4*)Qs)[tid] = ((const uint4*)(g_q + ((size_t)bb * HW + n0) * 4))[tid];
    if (tid < 128) cpa16(ksa[1] + tid * 16, kgm + 512 + tid * 4);
#pragma unroll
    for (int j = 0; j < 4; ++j)
        cpa16(vsa[1] + (tid + j * 256) * 16, vgm + 4096 + (tid + j * 256) * 4);
    asm volatile("cp.async.commit_group;");
    __syncthreads();

    int r0i = w * 16 + g;
    uint32_t qa0 = Qs[r0i * 4 + t];
    uint32_t qa1 = Qs[(r0i + 8) * 4 + t];
    uint32_t qb0 = Qs[(r0i + 128) * 4 + t];
    uint32_t qb1 = Qs[(r0i + 136) * 4 + t];

    int midx = lane >> 3;
    int lane_const = (midx & 1) * 8 + (midx >> 1);
    uint32_t lboff = (uint32_t)((lane_const * 32 + (lane & 7) * 4) * 4);
    uint32_t kfoff = (uint32_t)((((lane >> 3) * 8 + (lane & 7)) * 16));

    float o[16][4];
#pragma unroll
    for (int nb = 0; nb < 16; ++nb) { o[nb][0] = o[nb][1] = o[nb][2] = o[nb][3] = 0.f; }
    float zc0[4] = {0.f, 0.f, 0.f, 0.f};
    float zc1[4] = {0.f, 0.f, 0.f, 0.f};
    const uint32_t ONES = 0x3C003C00u;

    int cur = 0, pf = 2;
#pragma unroll 1
    for (int it = 0; it < 32; ++it) {
        if (it < 31) asm volatile("cp.async.wait_group 1;");
        else         asm volatile("cp.async.wait_group 0;");
        __syncthreads();
        uint32_t kb_base = ksa[cur] + kfoff;
        uint32_t lb = vsa[cur] + lboff;

        // K fragments shared by both query blocks
        uint32_t kf[16];
#pragma unroll
        for (int j4 = 0; j4 < 4; ++j4)
            ldsm_x4(kf[4 * j4], kf[4 * j4 + 1], kf[4 * j4 + 2], kf[4 * j4 + 3],
                    kb_base + (uint32_t)(j4 * 512));

#pragma unroll
        for (int half = 0; half < 2; ++half) {
            uint32_t ua0 = half ? qb0 : qa0;
            uint32_t ua1 = half ? qb1 : qa1;
            float* oo = &o[half * 8][0];
            float* zz = half ? zc1 : zc0;
            uint32_t pa[16][2];
#pragma unroll
            for (int j = 0; j < 16; ++j) {
                uint32_t d0, d1;
                mma_f16k8h(d0, d1, ua0, ua1, kf[j]);
                pa[j][0] = ex2h2(d0);
                pa[j][1] = ex2h2(d1);
            }
#pragma unroll
            for (int ks = 0; ks < 8; ++ks) {
#pragma unroll
                for (int nbp = 0; nbp < 4; ++nbp) {
                    uint32_t b00, b10, b01, b11;
                    ldsm_x4(b00, b10, b01, b11, lb + (uint32_t)((16 * ks + 2 * nbp) * 128));
                    mma_f16(&oo[(2 * nbp) * 4], pa[2 * ks][0], pa[2 * ks][1],
                            pa[2 * ks + 1][0], pa[2 * ks + 1][1], b00, b10);
                    mma_f16(&oo[(2 * nbp + 1) * 4], pa[2 * ks][0], pa[2 * ks][1],
                            pa[2 * ks + 1][0], pa[2 * ks + 1][1], b01, b11);
                }
                mma_f16(zz, pa[2 * ks][0], pa[2 * ks][1],
                        pa[2 * ks + 1][0], pa[2 * ks + 1][1], ONES, ONES);
            }
        }
        if (it + 2 < 32) {
            int t2 = it + 2;
            if (tid < 128) cpa16(ksa[pf] + tid * 16, kgm + (size_t)t2 * 512 + tid * 4);
#pragma unroll
            for (int j = 0; j < 4; ++j)
                cpa16(vsa[pf] + (tid + j * 256) * 16,
                      vgm + (size_t)t2 * 4096 + (tid + j * 256) * 4);
            asm volatile("cp.async.commit_group;");
        }
        cur = (cur == 2) ? 0 : cur + 1;
        pf = (pf == 2) ? 0 : pf + 1;
    }
    float ga = gamma[br];
#pragma unroll
    for (int half = 0; half < 2; ++half) {
        float* zz = half ? zc1 : zc0;
        float i0 = ga / zz[0], i1 = ga / zz[2];
        float* base0 = g_fused + ((size_t)b * HW + n0 + half * 128 + w * 16 + g) * 256
                     + br * 64 + 2 * t;
        float* base1 = base0 + 8 * 256;
#pragma unroll
        for (int nb = 0; nb < 8; ++nb) {
            float* oo = &o[half * 8 + nb][0];
            float2 v0 = *(float2*)(base0 + nb * 8);
            v0.x += oo[0] * i0; v0.y += oo[1] * i0;
            *(float2*)(base0 + nb * 8) = v0;
            float2 v1 = *(float2*)(base1 + nb * 8);
            v1.x += oo[2] * i1; v1.y += oo[3] * i1;
            *(float2*)(base1 + nb * 8) = v1;
        }
    }
}

// ---------------- K4: pool (unchanged) -------------------------------------
template<int PS, int PLO>
__device__ __forceinline__ float4 pool_win4(int b, int oy, int ox, int c4) {
    int ys0 = oy * PS - PLO, xs0 = ox * PS - PLO;
    float4 s = make_float4(0.f, 0.f, 0.f, 0.f);
    int cnt = 0;
#pragma unroll
    for (int dy = 0; dy < PS; ++dy) {
        int yy = ys0 + dy;
        bool vy = (unsigned)yy < 64u;
        int yyc = min(max(yy, 0), 63);
#pragma unroll
        for (int dx = 0; dx < PS; ++dx) {
            int xx = xs0 + dx;
            bool v = vy && ((unsigned)xx < 64u);
            int xxc = min(max(xx, 0), 63);
            float4 val = *(const float4*)(g_fused + ((size_t)(b * HW) + yyc * 64 + xxc) * 256 + c4);
            if (v) { s.x += val.x; s.y += val.y; s.z += val.z; s.w += val.w; ++cnt; }
        }
    }
    float inv = 1.f / (float)cnt;
    s.x *= inv; s.y *= inv; s.z *= inv; s.w *= inv;
    return s;
}

__global__ void k_pool(const float* __restrict__ pw, const float* __restrict__ pb,
                       const float* __restrict__ pg, const float* __restrict__ pbe,
                       const float* __restrict__ pm, const float* __restrict__ pv) {
    __shared__ float avg[4][256];
    __shared__ float part[4][64];
    int b = blockIdx.y;
    int slot = threadIdx.x >> 6;
    int l64 = threadIdx.x & 63;
    int lin = blockIdx.x * 4 + slot;
    bool valid = lin < 1629;
    int linc = valid ? lin : 1628;
    int j, r;
    if (linc < 1024)      { j = 1; r = linc; }
    else if (linc < 1508) { j = 2; r = linc - 1024; }
    else                  { j = 3; r = linc - 1508; }
    const int HPs[4] = {64, 32, 22, 11};
    int hp = HPs[j];
    int oy = r / hp, ox = r % hp;
    int c4 = l64 * 4;
    float4 s;
    if (j == 1)      s = pool_win4<2, 0>(b, oy, ox, c4);
    else if (j == 2) s = pool_win4<3, 1>(b, oy, ox, c4);
    else             s = pool_win4<6, 1>(b, oy, ox, c4);
    *(float4*)&avg[slot][c4] = s;
    __syncthreads();
    int o = l64 & 15, q = l64 >> 4;
    const float* wp = pw + j * 4096 + o;
    float a = 0.f;
#pragma unroll 16
    for (int i = 0; i < 64; ++i) {
        int ci = q * 64 + i;
        a += avg[slot][ci] * wp[ci * 16];
    }
    part[slot][q * 16 + o] = a;
    __syncthreads();
    if (l64 < 16 && valid) {
        float acc = pb[j * 16 + l64] + part[slot][l64] + part[slot][16 + l64]
                  + part[slot][32 + l64] + part[slot][48 + l64];
        int idx = j * 16 + l64;
        float sc = pg[idx] * rsqrtf(pv[idx] + 1e-3f);
        float sh = pbe[idx] - pm[idx] * sc;
        g_pool[((size_t)((j * 2 + b) * HW) + oy * hp + ox) * 16 + l64] = acc * sc + sh;
    }
}

// ---------------- K5: proj GEMM (unchanged) --------------------------------
__global__ void __launch_bounds__(256) k_proj(
        const float* __restrict__ w, const float* __restrict__ pb,
        const float* __restrict__ g2, const float* __restrict__ be,
        const float* __restrict__ m, const float* __restrict__ v,
        const float* __restrict__ pplw, const float* __restrict__ pplb,
        const float* __restrict__ ppg, const float* __restrict__ ppbe,
        const float* __restrict__ ppm, const float* __restrict__ ppv,
        float* __restrict__ out) {
    extern __shared__ uint32_t dyn[];
    uint32_t* W2 = dyn + 19584;
    float* scs2 = (float*)(dyn + 23936);
    float* shs2 = (float*)(dyn + 24000);
    float* psc = (float*)(dyn + 24064);
    float* psh = (float*)(dyn + 24080);

    int tid = threadIdx.x;
    int tok0 = blockIdx.x * 64;
    int b2 = tok0 >> 12;
    int yy = (tok0 & 4095) >> 6;
    int w_ = tid >> 5, lane = tid & 31;
    int wm = w_ & 3, wn = w_ >> 2;
    int g = lane >> 2, t = lane & 3;
    int m0 = wm * 16;

    int p4 = tid >> 2, cs = (tid & 3) * 16;
    const float* asrc = g_fused + (size_t)(tok0 + p4) * 256 + cs;
    float4 ar[4];
    int wcl = tid >> 4, wco4 = (tid & 15) * 4;
    int wsc4 = wco4 + (wco4 >= 32 ? 8 : 0);
    int qcl = tid >> 2, qo4 = (tid & 3) * 4;
    int qsc4 = (qo4 < 8) ? (32 + qo4) : (64 + qo4);

#define LOADA(ck) do {                                                      \
        const float* s_ = asrc + (ck) * 64;                                 \
        ar[0] = *(const float4*)(s_);      ar[1] = *(const float4*)(s_ + 4); \
        ar[2] = *(const float4*)(s_ + 8);  ar[3] = *(const float4*)(s_ + 12); \
    } while (0)
#define STOREA(bi) do {                                                     \
        uint32_t* d_ = dyn + (bi) * 4352 + p4 * 68 + cs;                    \
        _Pragma("unroll")                                                   \
        for (int i_ = 0; i_ < 4; ++i_) {                                    \
            *(uint2*)(d_ + i_ * 4) =                                        \
                make_uint2(f2tf32(ar[i_].x), f2tf32(ar[i_].y));             \
            *(uint2*)(d_ + i_ * 4 + 2) =                                    \
                make_uint2(f2tf32(ar[i_].z), f2tf32(ar[i_].w));             \
        }                                                                   \
    } while (0)

    LOADA(0); STOREA(0);
    {
        uint32_t* Wb0 = dyn + 8704;
#pragma unroll
        for (int i = 0; i < 4; ++i) {
            int cl = wcl + i * 16;
            float4 vv = *(const float4*)(w + cl * 64 + wco4);
            Wb0[(wsc4 + 0) * 68 + cl] = f2tf32(vv.x);
            Wb0[(wsc4 + 1) * 68 + cl] = f2tf32(vv.y);
            Wb0[(wsc4 + 2) * 68 + cl] = f2tf32(vv.z);
            Wb0[(wsc4 + 3) * 68 + cl] = f2tf32(vv.w);
        }
        float4 vv = *(const float4*)(pplw + qcl * 16 + qo4);
        Wb0[(qsc4 + 0) * 68 + qcl] = f2tf32(vv.x);
        Wb0[(qsc4 + 1) * 68 + qcl] = f2tf32(vv.y);
        Wb0[(qsc4 + 2) * 68 + qcl] = f2tf32(vv.z);
        Wb0[(qsc4 + 3) * 68 + qcl] = f2tf32(vv.w);
    }
#pragma unroll
    for (int i = 0; i < 4; ++i) {
        int id = tid + i * 256;
        int k = id >> 4, co4 = (id & 15) * 4;
        float4 vv = *(const float4*)(w + (256 + k) * 64 + co4);
        W2[(co4 + 0) * 68 + k] = f2tf32(vv.x);
        W2[(co4 + 1) * 68 + k] = f2tf32(vv.y);
        W2[(co4 + 2) * 68 + k] = f2tf32(vv.z);
        W2[(co4 + 3) * 68 + k] = f2tf32(vv.w);
    }
    if (tid < 64) {
        float sc = g2[tid] * rsqrtf(v[tid] + 1e-3f);
        scs2[tid] = sc;
        shs2[tid] = be[tid] - m[tid] * sc + pb[tid] * sc;
    } else if (tid < 80) {
        int o = tid - 64;
        float sc = ppg[o] * rsqrtf(ppv[o] + 1e-3f);
        psc[o] = sc;
        psh[o] = ppbe[o] - ppm[o] * sc + pplb[o] * sc;
    }
    LOADA(1);
    __syncthreads();

    float a1c[5][4];
#pragma unroll
    for (int nb = 0; nb < 5; ++nb) a1c[nb][0] = a1c[nb][1] = a1c[nb][2] = a1c[nb][3] = 0.f;
    int wn40 = wn * 40;
#pragma unroll 1
    for (int ck = 0; ck < 4; ++ck) {
        float4 wrp[4], wrq;
        if (ck + 1 < 4) {
            int cb = (ck + 1) * 64;
#pragma unroll
            for (int i = 0; i < 4; ++i)
                wrp[i] = *(const float4*)(w + (cb + wcl + i * 16) * 64 + wco4);
            wrq = *(const float4*)(pplw + (cb + qcl) * 16 + qo4);
        }
        const uint32_t* Ab = dyn + (ck & 1) * 4352;
        const uint32_t* Ar0 = Ab + (m0 + g) * 68 + t;
        const uint32_t* Ar1 = Ab + (m0 + g + 8) * 68 + t;
        const uint32_t* Wc = dyn + 8704 + (ck & 1) * 5440 + (wn40 + g) * 68 + t;
#pragma unroll
        for (int k0 = 0; k0 < 64; k0 += 8) {
            uint32_t a0 = Ar0[k0], a1 = Ar1[k0];
            uint32_t a2 = Ar0[k0 + 4], a3 = Ar1[k0 + 4];
#pragma unroll
            for (int nb = 0; nb < 5; ++nb)
                mma_tf32(a1c[nb], a0, a1, a2, a3,
                         Wc[nb * 544 + k0], Wc[nb * 544 + k0 + 4]);
        }
        if (ck + 1 < 4) {
            uint32_t* Wn = dyn + 8704 + ((ck + 1) & 1) * 5440;
#pragma unroll
            for (int i = 0; i < 4; ++i) {
                int cl = wcl + i * 16;
                Wn[(wsc4 + 0) * 68 + cl] = f2tf32(wrp[i].x);
                Wn[(wsc4 + 1) * 68 + cl] = f2tf32(wrp[i].y);
                Wn[(wsc4 + 2) * 68 + cl] = f2tf32(wrp[i].z);
                Wn[(wsc4 + 3) * 68 + cl] = f2tf32(wrp[i].w);
            }
            Wn[(qsc4 + 0) * 68 + qcl] = f2tf32(wrq.x);
            Wn[(qsc4 + 1) * 68 + qcl] = f2tf32(wrq.y);
            Wn[(qsc4 + 2) * 68 + qcl] = f2tf32(wrq.z);
            Wn[(qsc4 + 3) * 68 + qcl] = f2tf32(wrq.w);
            STOREA((ck + 1) & 1);
        }
        __syncthreads();
        if (ck + 2 < 4) LOADA(ck + 2);
    }
#undef LOADA
#undef STOREA

    uint32_t* X2 = dyn;
    {
        int o = wn * 8 + 2 * t;
        float s0 = psc[o], s1 = psc[o + 1], h0 = psh[o], h1 = psh[o + 1];
        *(uint2*)&X2[(m0 + g) * 68 + o] =
            make_uint2(f2tf32(a1c[4][0] * s0 + h0), f2tf32(a1c[4][1] * s1 + h1));
        *(uint2*)&X2[(m0 + g + 8) * 68 + o] =
            make_uint2(f2tf32(a1c[4][2] * s0 + h0), f2tf32(a1c[4][3] * s1 + h1));
    }
    {
        const int HP[3] = {32, 22, 11};
#pragma unroll
        for (int lvl = 0; lvl < 3; ++lvl) {
            int hp = HP[lvl];
            float scale = hp * (1.f / 64.f);
            const float* P0 = g_pool + (size_t)(((lvl + 1) * 2 + b2) * HW) * 16;
            float fy = (yy + 0.5f) * scale - 0.5f;
            float y0f = floorf(fy);
            float ty = fy - y0f;
            int yA = min(max((int)y0f, 0), hp - 1);
            int yB = min(max((int)y0f + 1, 0), hp - 1);
#pragma unroll
            for (int i = 0; i < 4; ++i) {
                int id = tid + i * 256;
                int px = id >> 4, c = id & 15;
                float fx = (px + 0.5f) * scale - 0.5f;
                float x0f = floorf(fx);
                float tx = fx - x0f;
                int xA = min(max((int)x0f, 0), hp - 1);
                int xB = min(max((int)x0f + 1, 0), hp - 1);
                const float* P = P0 + c;
                float v00 = P[(yA * hp + xA) * 16], v01 = P[(yA * hp + xB) * 16];
                float v10 = P[(yB * hp + xA) * 16], v11 = P[(yB * hp + xB) * 16];
                float val = (1.f - ty) * ((1.f - tx) * v00 + tx * v01)
                          + ty * ((1.f - tx) * v10 + tx * v11);
                X2[px * 68 + 16 + lvl * 16 + c] = f2tf32(val);
            }
        }
    }
    __syncthreads();

    float a2c[4][4];
#pragma unroll
    for (int nb = 0; nb < 4; ++nb) a2c[nb][0] = a2c[nb][1] = a2c[nb][2] = a2c[nb][3] = 0.f;
    {
        const uint32_t* Ar0 = X2 + (m0 + g) * 68 + t;
        const uint32_t* Ar1 = X2 + (m0 + g + 8) * 68 + t;
        const uint32_t* Wc = W2 + (wn * 32 + g) * 68 + t;
#pragma unroll
        for (int k0 = 0; k0 < 64; k0 += 8) {
            uint32_t a0 = Ar0[k0], a1 = Ar1[k0];
            uint32_t a2 = Ar0[k0 + 4], a3 = Ar1[k0 + 4];
#pragma unroll
            for (int nb = 0; nb < 4; ++nb)
                mma_tf32(a2c[nb], a0, a1, a2, a3,
                         Wc[nb * 544 + k0], Wc[nb * 544 + k0 + 4]);
        }
    }
    float* o0 = out + (size_t)(tok0 + m0 + g) * 64;
    float* o1 = o0 + 8 * 64;
#pragma unroll
    for (int nb = 0; nb < 4; ++nb) {
        int col = wn * 32 + nb * 8 + 2 * t;
        float s0 = scs2[col], s1 = scs2[col + 1];
        float h0 = shs2[col], h1 = shs2[col + 1];
        float2 r0, r1;
        r0.x = fmaxf((a1c[nb][0] + a2c[nb][0]) * s0 + h0, 0.f);
        r0.y = fmaxf((a1c[nb][1] + a2c[nb][1]) * s1 + h1, 0.f);
        r1.x = fmaxf((a1c[nb][2] + a2c[nb][2]) * s0 + h0, 0.f);
        r1.y = fmaxf((a1c[nb][3] + a2c[nb][3]) * s1 + h1, 0.f);
        *(float2*)(o0 + col) = r0;
        *(float2*)(o1 + col) = r1;
    }
}

// ---------------- launch ---------------------------------------------------
extern "C" void kernel_launch(void* const* d_in, const int* in_sizes, int n_in,
                              void* d_out, int out_size) {
    const float* x       = (const float*)d_in[0];
    const float* conv_w  = (const float*)d_in[1];
    const float* conv_b  = (const float*)d_in[2];
    const float* bn_g    = (const float*)d_in[3];
    const float* bn_b    = (const float*)d_in[4];
    const float* bn_m    = (const float*)d_in[5];
    const float* bn_v    = (const float*)d_in[6];
    const float* q_w     = (const float*)d_in[7];
    const float* q_b     = (const float*)d_in[8];
    const float* k_w     = (const float*)d_in[9];
    const float* k_b     = (const float*)d_in[10];
    const float* v_w     = (const float*)d_in[11];
    const float* v_b     = (const float*)d_in[12];
    const float* attn_g  = (const float*)d_in[13];
    const float* ppl_w   = (const float*)d_in[14];
    const float* ppl_b   = (const float*)d_in[15];
    const float* ppl_bng = (const float*)d_in[16];
    const float* ppl_bnb = (const float*)d_in[17];
    const float* ppl_bnm = (const float*)d_in[18];
    const float* ppl_bnv = (const float*)d_in[19];
    const float* proj_w  = (const float*)d_in[20];
    const float* proj_b  = (const float*)d_in[21];
    const float* pbn_g   = (const float*)d_in[22];
    const float* pbn_b   = (const float*)d_in[23];
    const float* pbn_m   = (const float*)d_in[24];
    const float* pbn_v   = (const float*)d_in[25];
    float* out = (float*)d_out;

    const int CONV_SMEM = 26240 * 4;   // 104,960 B
    const int ATTN_SMEM = 14848 * 4;   // 59,392 B
    const int PROJ_SMEM = 24096 * 4;   // 96,384 B
    cudaFuncSetAttribute(k_conv, cudaFuncAttributeMaxDynamicSharedMemorySize, CONV_SMEM);
    cudaFuncSetAttribute(k_attn, cudaFuncAttributeMaxDynamicSharedMemorySize, ATTN_SMEM);
    cudaFuncSetAttribute(k_proj, cudaFuncAttributeMaxDynamicSharedMemorySize, PROJ_SMEM);

    k_conv<<<dim3(32, 8), 256, CONV_SMEM>>>(x, conv_w, conv_b, bn_g, bn_b, bn_m, bn_v,
                                            q_w, q_b, k_w, k_b, v_w, v_b);
    k_attn<<<dim3(16, 4, 2), 256, ATTN_SMEM>>>(attn_g);
    k_pool<<<dim3(408, 2), 256>>>(ppl_w, ppl_b, ppl_bng, ppl_bnb, ppl_bnm, ppl_bnv);
    k_proj<<<128, 256, PROJ_SMEM>>>(proj_w, proj_b, pbn_g, pbn_b, pbn_m, pbn_v,
                                    ppl_w, ppl_b, ppl_bng, ppl_bnb, ppl_bnm, ppl_bnv, out);
}